// round 13
// baseline (speedup 1.0000x reference)
#include <cuda_runtime.h>
#include <cstdint>

#define NN   100000
#define EE   1600000
#define BB   512
#define EPN  200000
#define NINK 64
#define HID  72
#define EPSBN 1e-5f
#define SCAN_BLKS ((NN + 1023) / 1024)   // 98

// ---------------- scratch (device globals) ----------------
__device__ __align__(16) int      g_degi[NN];
__device__ __align__(16) int      g_cur[NN];
__device__ __align__(16) int      g_offi[NN];
__device__ __align__(16) int      g_offx[NN + 1];
__device__ __align__(16) int      g_bsum[SCAN_BLKS + 1];
__device__ __align__(16) float    g_norm[EE];
__device__ __align__(16) int2     g_csr[EE];       // (src row, norm bits), dest-sorted
__device__ __align__(16) float    g_h[NN * HID];
__device__ __align__(16) float    g_t[NN * HID];
__device__ __align__(16) float    g_acc[NN * HID];
__device__ __align__(16) float    g_e[NN * HID];
__device__ __align__(16) float    g_sum[HID];
__device__ __align__(16) float    g_sq[HID];
__device__ __align__(16) float    g_scale[HID];
__device__ __align__(16) float    g_shift[HID];
__device__ __align__(16) float    g_p1[BB * 2 * HID];
__device__ __align__(16) unsigned g_p2[BB * 2 * HID];
__device__ __align__(16) float    g_cnt[BB];
__device__ __align__(16) float    g_Ya[BB * HID];
__device__ __align__(16) float    g_Yb[BB * HID];

__device__ __forceinline__ unsigned fenc(float f) {
    unsigned u = __float_as_uint(f);
    return (u & 0x80000000u) ? ~u : (u | 0x80000000u);
}
__device__ __forceinline__ float fdec(unsigned u) {
    return (u & 0x80000000u) ? __uint_as_float(u ^ 0x80000000u) : __uint_as_float(~u);
}
#define ENC_NEG_INF 0x007FFFFFu

// ---------------- resets ----------------
__global__ void reset_graph() {
    int i = blockIdx.x * blockDim.x + threadIdx.x;
    if (i < NN) { g_degi[i] = 0; g_cur[i] = 0; }
}
__global__ void reset_bnstats() {
    int i = threadIdx.x;
    if (i < HID) { g_sum[i] = 0.f; g_sq[i] = 0.f; }
}
__global__ void reset_pool() {
    int i = blockIdx.x * blockDim.x + threadIdx.x;
    if (i < BB * 2 * HID) { g_p1[i] = 0.f; g_p2[i] = ENC_NEG_INF; }
    if (i < BB) g_cnt[i] = 0.f;
}

// ---------------- degree / norm ----------------
__global__ void degree_kernel(const int* __restrict__ eidx) {
    int i = blockIdx.x * blockDim.x + threadIdx.x;
    if (i < EE) atomicAdd(&g_degi[eidx[EE + i]], 1);
}
__global__ void norm_kernel(const int* __restrict__ eidx) {
    int i = blockIdx.x * blockDim.x + threadIdx.x;
    if (i >= EE) return;
    int dr = g_degi[eidx[i]];
    int dc = g_degi[eidx[EE + i]];
    float a = dr > 0 ? rsqrtf((float)dr) : 0.f;
    float b = dc > 0 ? rsqrtf((float)dc) : 0.f;
    g_norm[i] = a * b;
}

// ---------------- CSR build ----------------
__global__ void scan_block() {
    __shared__ int s[1024];
    int i = blockIdx.x * 1024 + threadIdx.x;
    int v = (i < NN) ? g_degi[i] : 0;
    s[threadIdx.x] = v;
    __syncthreads();
#pragma unroll
    for (int off = 1; off < 1024; off <<= 1) {
        int x = (threadIdx.x >= off) ? s[threadIdx.x - off] : 0;
        __syncthreads();
        s[threadIdx.x] += x;
        __syncthreads();
    }
    if (i < NN) g_offi[i] = s[threadIdx.x];
    if (threadIdx.x == 1023) g_bsum[blockIdx.x] = s[1023];
}
__global__ void scan_bsum() {
    if (threadIdx.x == 0) {
        int run = 0;
        for (int b = 0; b < SCAN_BLKS; b++) { int v = g_bsum[b]; g_bsum[b] = run; run += v; }
        g_offx[NN] = EE;
    }
}
__global__ void scan_fix() {
    int i = blockIdx.x * blockDim.x + threadIdx.x;
    if (i < NN) g_offx[i] = g_offi[i] - g_degi[i] + g_bsum[i >> 10];
}
__global__ void csr_fill(const int* __restrict__ eidx) {
    int e = blockIdx.x * 256 + threadIdx.x;
    int row = eidx[e], col = eidx[EE + e];
    int pos = g_offx[col] + atomicAdd(&g_cur[col], 1);
    g_csr[pos] = make_int2(row, __float_as_int(g_norm[e]));
}

// ---------------- input GEMM: 96 thr = 32 rowslots(TM=2) x 3 colgroups(24) ----------
template <int K, int DST>
__global__ __launch_bounds__(96) void gemm_in_relu(const float* __restrict__ in,
                                                   const float* __restrict__ W,
                                                   const float* __restrict__ bias) {
    float* __restrict__ out = (DST == 0) ? g_h : g_e;
    const int ROWS = 64;
    __shared__ __align__(16) float s_in[ROWS * (K + 1)];
    __shared__ __align__(16) float s_w[K * HID];
    const int tid = threadIdx.x;
    const int colg = tid / 32;           // 0..2
    const int rs = tid & 31;             // row slot: rows rs, rs+32
    const int c0 = colg * 24;
    int row0 = blockIdx.x * ROWS;
    for (int idx = tid; idx < ROWS * K; idx += 96) {
        int r = idx / K, c = idx - r * K;
        int g = (row0 + r) * K + c;
        s_in[r * (K + 1) + c] = (row0 + r < NN) ? in[g] : 0.f;
    }
    for (int idx = tid; idx < K * HID; idx += 96) s_w[idx] = W[idx];
    __syncthreads();
    float acc0[24], acc1[24];
#pragma unroll
    for (int j = 0; j < 24; j++) { acc0[j] = bias[c0 + j]; acc1[j] = acc0[j]; }
    for (int k = 0; k < K; k++) {
        float a0 = s_in[rs * (K + 1) + k];
        float a1 = s_in[(rs + 32) * (K + 1) + k];
#pragma unroll
        for (int j = 0; j < 24; j += 4) {
            float4 w = *(const float4*)&s_w[k * HID + c0 + j];
            acc0[j + 0] += a0 * w.x; acc0[j + 1] += a0 * w.y;
            acc0[j + 2] += a0 * w.z; acc0[j + 3] += a0 * w.w;
            acc1[j + 0] += a1 * w.x; acc1[j + 1] += a1 * w.y;
            acc1[j + 2] += a1 * w.z; acc1[j + 3] += a1 * w.w;
        }
    }
    int r0 = row0 + rs, r1 = row0 + rs + 32;
    if (r0 < NN) {
        float4* o = reinterpret_cast<float4*>(out + r0 * HID + c0);
#pragma unroll
        for (int j = 0; j < 24; j += 4)
            o[j / 4] = make_float4(fmaxf(acc0[j], 0.f), fmaxf(acc0[j + 1], 0.f),
                                   fmaxf(acc0[j + 2], 0.f), fmaxf(acc0[j + 3], 0.f));
    }
    if (r1 < NN) {
        float4* o = reinterpret_cast<float4*>(out + r1 * HID + c0);
#pragma unroll
        for (int j = 0; j < 24; j += 4)
            o[j / 4] = make_float4(fmaxf(acc1[j], 0.f), fmaxf(acc1[j + 1], 0.f),
                                   fmaxf(acc1[j + 2], 0.f), fmaxf(acc1[j + 3], 0.f));
    }
}

// ---------------- conv GEMMs: t = h@Wi ; acc = h@Wr + bias (TM=2 x 3 colgroups) -----
template <bool BN>
__global__ __launch_bounds__(96) void conv_gemm(const float* __restrict__ Wi,
                                                const float* __restrict__ Wr,
                                                const float* __restrict__ bias) {
    const int ROWS = 64;
    const int K = HID;
    __shared__ __align__(16) float s_in[ROWS * (K + 1)];
    __shared__ __align__(16) float s_w[K * HID];
    const int tid = threadIdx.x;
    const int colg = tid / 32;
    const int rs = tid & 31;
    const int c0 = colg * 24;
    int row0 = blockIdx.x * ROWS;
    for (int idx = tid; idx < ROWS * K; idx += 96) {
        int r = idx / K, c = idx - r * K;
        float v = (row0 + r < NN) ? g_h[(row0 + r) * K + c] : 0.f;
        if (BN) v = v * g_scale[c] + g_shift[c];
        s_in[r * (K + 1) + c] = v;
    }
    for (int idx = tid; idx < K * HID; idx += 96) s_w[idx] = Wi[idx];
    __syncthreads();
    int r0 = row0 + rs, r1 = row0 + rs + 32;
    float acc0[24], acc1[24];
#pragma unroll
    for (int j = 0; j < 24; j++) { acc0[j] = 0.f; acc1[j] = 0.f; }
    for (int k = 0; k < K; k++) {
        float a0 = s_in[rs * (K + 1) + k];
        float a1 = s_in[(rs + 32) * (K + 1) + k];
#pragma unroll
        for (int j = 0; j < 24; j += 4) {
            float4 w = *(const float4*)&s_w[k * HID + c0 + j];
            acc0[j + 0] += a0 * w.x; acc0[j + 1] += a0 * w.y;
            acc0[j + 2] += a0 * w.z; acc0[j + 3] += a0 * w.w;
            acc1[j + 0] += a1 * w.x; acc1[j + 1] += a1 * w.y;
            acc1[j + 2] += a1 * w.z; acc1[j + 3] += a1 * w.w;
        }
    }
    if (r0 < NN) {
        float4* o = reinterpret_cast<float4*>(g_t + r0 * HID + c0);
#pragma unroll
        for (int j = 0; j < 24; j += 4)
            o[j / 4] = make_float4(acc0[j], acc0[j + 1], acc0[j + 2], acc0[j + 3]);
    }
    if (r1 < NN) {
        float4* o = reinterpret_cast<float4*>(g_t + r1 * HID + c0);
#pragma unroll
        for (int j = 0; j < 24; j += 4)
            o[j / 4] = make_float4(acc1[j], acc1[j + 1], acc1[j + 2], acc1[j + 3]);
    }
    __syncthreads();
    for (int idx = tid; idx < K * HID; idx += 96) s_w[idx] = Wr[idx];
    __syncthreads();
#pragma unroll
    for (int j = 0; j < 24; j++) { acc0[j] = bias[c0 + j]; acc1[j] = acc0[j]; }
    for (int k = 0; k < K; k++) {
        float a0 = s_in[rs * (K + 1) + k];
        float a1 = s_in[(rs + 32) * (K + 1) + k];
#pragma unroll
        for (int j = 0; j < 24; j += 4) {
            float4 w = *(const float4*)&s_w[k * HID + c0 + j];
            acc0[j + 0] += a0 * w.x; acc0[j + 1] += a0 * w.y;
            acc0[j + 2] += a0 * w.z; acc0[j + 3] += a0 * w.w;
            acc1[j + 0] += a1 * w.x; acc1[j + 1] += a1 * w.y;
            acc1[j + 2] += a1 * w.z; acc1[j + 3] += a1 * w.w;
        }
    }
    if (r0 < NN) {
        float4* o = reinterpret_cast<float4*>(g_acc + r0 * HID + c0);
#pragma unroll
        for (int j = 0; j < 24; j += 4)
            o[j / 4] = make_float4(acc0[j], acc0[j + 1], acc0[j + 2], acc0[j + 3]);
    }
    if (r1 < NN) {
        float4* o = reinterpret_cast<float4*>(g_acc + r1 * HID + c0);
#pragma unroll
        for (int j = 0; j < 24; j += 4)
            o[j / 4] = make_float4(acc1[j], acc1[j + 1], acc1[j + 2], acc1[j + 3]);
    }
}

// ---------------- gather: acc[n] += sum norm_e * t[src_e] ----------------
__global__ __launch_bounds__(288) void gather_edges() {
    int tid = threadIdx.x;
    int node = blockIdx.x * 16 + tid / 18;
    int ch = (tid % 18) * 4;
    if (node >= NN) return;
    int p = g_offx[node];
    int end = g_offx[node + 1];
    float* ap = g_acc + node * HID + ch;
    float4 acc = *(float4*)ap;
    if (p < end) {
        int2 rc = g_csr[p];
        for (; p < end; p++) {
            int2 nrc = (p + 1 < end) ? g_csr[p + 1] : rc;
            float nrm = __int_as_float(rc.y);
            float4 v = *(const float4*)(g_t + rc.x * HID + ch);
            acc.x += nrm * v.x; acc.y += nrm * v.y;
            acc.z += nrm * v.z; acc.w += nrm * v.w;
            rc = nrc;
        }
    }
    *(float4*)ap = acc;
}

// ---------------- batchnorm stats: h <- relu(acc); per-channel sum/sq ----------------
__global__ __launch_bounds__(288) void bn_stats() {
    int tid = threadIdx.x;
    int c = tid % HID, rg = tid / HID;
    float lsum = 0.f, lsq = 0.f;
    for (int r = blockIdx.x * 4 + rg; r < NN; r += gridDim.x * 4) {
        float v = fmaxf(g_acc[r * HID + c], 0.f);
        g_h[r * HID + c] = v;
        lsum += v; lsq += v * v;
    }
    __shared__ float ssum[288], ssq[288];
    ssum[tid] = lsum; ssq[tid] = lsq;
    __syncthreads();
    if (tid < HID) {
        float s = ssum[tid] + ssum[tid + 72] + ssum[tid + 144] + ssum[tid + 216];
        float q = ssq[tid] + ssq[tid + 72] + ssq[tid + 144] + ssq[tid + 216];
        atomicAdd(&g_sum[tid], s);
        atomicAdd(&g_sq[tid], q);
    }
}
__global__ void bn_finalize(const float* __restrict__ gamma, const float* __restrict__ beta) {
    int c = threadIdx.x;
    if (c >= HID) return;
    float mu = g_sum[c] * (1.0f / NN);
    float var = g_sq[c] * (1.0f / NN) - mu * mu;
    float inv = rsqrtf(var + EPSBN);
    float sc = inv * gamma[c];
    g_scale[c] = sc;
    g_shift[c] = beta[c] - mu * sc;
}

// ---------------- pooling (layer-3 BN fused into h read) ----------------
__global__ void pool_kernel(const float* __restrict__ assign) {
    int w = (blockIdx.x * blockDim.x + threadIdx.x) >> 5;
    int lane = threadIdx.x & 31;
    if (w >= NN) return;
    const float* a = assign + (size_t)w * BB;
    float best = -__int_as_float(0x7f800000);
    int bi = 0x7fffffff;
    for (int j = lane; j < BB; j += 32) {
        float v = a[j];
        if (v > best) { best = v; bi = j; }
    }
#pragma unroll
    for (int off = 16; off; off >>= 1) {
        float ov = __shfl_xor_sync(0xffffffffu, best, off);
        int oi = __shfl_xor_sync(0xffffffffu, bi, off);
        if (ov > best || (ov == best && oi < bi)) { best = ov; bi = oi; }
    }
    int b = bi;
    for (int c = lane; c < 2 * HID; c += 32) {
        float zv;
        if (c < HID) zv = g_h[w * HID + c] * g_scale[c] + g_shift[c];
        else         zv = g_e[w * HID + (c - HID)];
        atomicAdd(&g_p1[b * (2 * HID) + c], zv);
        atomicMax(&g_p2[b * (2 * HID) + c], fenc(zv));
    }
    if (lane == 0) atomicAdd(&g_cnt[b], 1.0f);
}

// ---------------- xp build + factored pair-MLP first layer ----------------
__global__ void xp_kernel(const float* __restrict__ w1, const float* __restrict__ b1) {
    __shared__ float s_xp[6 * HID];
    int b = blockIdx.x;
    int t = threadIdx.x;  // 144
    float cnt = g_cnt[b];
    float p1v = g_p1[b * 144 + t];
    s_xp[t] = p1v;
    s_xp[144 + t] = fdec(g_p2[b * 144 + t]);
    s_xp[288 + t] = p1v / fmaxf(cnt, 1.0f);
    __syncthreads();
    int j = (t < HID) ? t : t - HID;
    const float* w = (t < HID) ? w1 : (w1 + 6 * HID * HID);
    float acc = (t < HID) ? b1[j] : 0.f;
    for (int k = 0; k < 6 * HID; k++) acc += s_xp[k] * w[k * HID + j];
    if (t < HID) g_Ya[b * HID + j] = acc;
    else         g_Yb[b * HID + j] = acc;
}

// ---------------- pair output ----------------
__global__ void pair_kernel(const int* __restrict__ pe, const float* __restrict__ w2,
                            const float* __restrict__ b2, float* __restrict__ out) {
    int w = (blockIdx.x * blockDim.x + threadIdx.x) >> 5;
    int lane = threadIdx.x & 31;
    if (w >= EPN) return;
    int a = pe[w];
    int b = pe[EPN + w];
    float acc = 0.f;
    for (int c = lane; c < HID; c += 32) {
        float v = g_Ya[a * HID + c] + g_Yb[b * HID + c];
        acc += tanhf(v) * w2[c];
    }
#pragma unroll
    for (int off = 16; off; off >>= 1) acc += __shfl_xor_sync(0xffffffffu, acc, off);
    if (lane == 0) out[w] = acc + b2[0];
}

// ---------------- launch (conv_gemm in profiled slot #4) ----------------
extern "C" void kernel_launch(void* const* d_in, const int* in_sizes, int n_in,
                              void* d_out, int out_size) {
    const float* x         = (const float*)d_in[0];
    const float* emb       = (const float*)d_in[1];
    const float* assign    = (const float*)d_in[2];
    const int*   eidx      = (const int*)d_in[3];
    const int*   pedge     = (const int*)d_in[4];
    const float* node_w    = (const float*)d_in[5];
    const float* node_b    = (const float*)d_in[6];
    const float* emb_w     = (const float*)d_in[7];
    const float* emb_b     = (const float*)d_in[8];
    const float* conv_wi   = (const float*)d_in[9];
    const float* conv_wr   = (const float*)d_in[10];
    const float* conv_bias = (const float*)d_in[11];
    const float* bn_gamma  = (const float*)d_in[12];
    const float* bn_beta   = (const float*)d_in[13];
    const float* mlp_w1    = (const float*)d_in[14];
    const float* mlp_b1    = (const float*)d_in[15];
    const float* mlp_w2    = (const float*)d_in[16];
    const float* mlp_b2    = (const float*)d_in[17];
    float*       out       = (float*)d_out;

    const int GB = (NN + 63) / 64;   // 1563

    reset_graph<<<(NN + 255) / 256, 256>>>();
    degree_kernel<<<EE / 256, 256>>>(eidx);
    gemm_in_relu<NINK, 0><<<GB, 96>>>(x, node_w, node_b);
    conv_gemm<false><<<GB, 96>>>(conv_wi, conv_wr, conv_bias);   // profiled slot
    norm_kernel<<<EE / 256, 256>>>(eidx);
    scan_block<<<SCAN_BLKS, 1024>>>();
    scan_bsum<<<1, 32>>>();
    scan_fix<<<(NN + 255) / 256, 256>>>();
    csr_fill<<<EE / 256, 256>>>(eidx);
    gemm_in_relu<NINK, 1><<<GB, 96>>>(emb, emb_w, emb_b);

    reset_bnstats<<<1, 128>>>();
    gather_edges<<<(NN + 15) / 16, 288>>>();
    bn_stats<<<1024, 288>>>();
    bn_finalize<<<1, 128>>>(bn_gamma, bn_beta);

    for (int l = 1; l < 3; l++) {
        conv_gemm<true><<<GB, 96>>>(conv_wi + l * HID * HID, conv_wr + l * HID * HID,
                                    conv_bias + l * HID);
        reset_bnstats<<<1, 128>>>();
        gather_edges<<<(NN + 15) / 16, 288>>>();
        bn_stats<<<1024, 288>>>();
        bn_finalize<<<1, 128>>>(bn_gamma + l * HID, bn_beta + l * HID);
    }

    reset_pool<<<(BB * 2 * HID + 255) / 256, 256>>>();
    pool_kernel<<<(NN * 32 + 255) / 256, 256>>>(assign);

    xp_kernel<<<BB, 144>>>(mlp_w1, mlp_b1);
    pair_kernel<<<(EPN * 32 + 255) / 256, 256>>>(pedge, mlp_w2, mlp_b2, out);
}

// round 14
// speedup vs baseline: 1.1939x; 1.1939x over previous
#include <cuda_runtime.h>
#include <cstdint>

#define NN   100000
#define EE   1600000
#define BB   512
#define EPN  200000
#define NINK 64
#define HID  72
#define EPSBN 1e-5f
#define SCAN_BLKS ((NN + 1023) / 1024)   // 98

// ---------------- scratch (device globals) ----------------
__device__ __align__(16) int      g_degi[NN];
__device__ __align__(16) int      g_cur[NN];
__device__ __align__(16) int      g_offi[NN];
__device__ __align__(16) int      g_offx[NN + 1];
__device__ __align__(16) int      g_bsum[SCAN_BLKS + 1];
__device__ __align__(16) float    g_norm[EE];
__device__ __align__(16) int2     g_csr[EE];       // (src row, norm bits), dest-sorted
__device__ __align__(16) float    g_h[NN * HID];
__device__ __align__(16) float    g_t[NN * HID];
__device__ __align__(16) float    g_acc[NN * HID];
__device__ __align__(16) float    g_e[NN * HID];
__device__ __align__(16) float    g_sum[HID];
__device__ __align__(16) float    g_sq[HID];
__device__ __align__(16) float    g_scale[HID];
__device__ __align__(16) float    g_shift[HID];
__device__ __align__(16) float    g_p1[BB * 2 * HID];
__device__ __align__(16) unsigned g_p2[BB * 2 * HID];
__device__ __align__(16) float    g_cnt[BB];
__device__ __align__(16) float    g_Ya[BB * HID];
__device__ __align__(16) float    g_Yb[BB * HID];

__device__ __forceinline__ unsigned fenc(float f) {
    unsigned u = __float_as_uint(f);
    return (u & 0x80000000u) ? ~u : (u | 0x80000000u);
}
__device__ __forceinline__ float fdec(unsigned u) {
    return (u & 0x80000000u) ? __uint_as_float(u ^ 0x80000000u) : __uint_as_float(~u);
}
#define ENC_NEG_INF 0x007FFFFFu

// ---------------- tf32 helpers ----------------
__device__ __forceinline__ unsigned f2tf(float x) {
    unsigned r;
    asm("cvt.rna.tf32.f32 %0, %1;" : "=r"(r) : "f"(x));
    return r;
}
__device__ __forceinline__ void tfsplit(float x, unsigned& hi, unsigned& lo) {
    asm("cvt.rna.tf32.f32 %0, %1;" : "=r"(hi) : "f"(x));
    float r = x - __uint_as_float(hi);
    asm("cvt.rna.tf32.f32 %0, %1;" : "=r"(lo) : "f"(r));
}
__device__ __forceinline__ void mma8(float* c, unsigned a0, unsigned a1, unsigned a2,
                                     unsigned a3, unsigned b0, unsigned b1) {
    asm volatile(
        "mma.sync.aligned.m16n8k8.row.col.f32.tf32.tf32.f32 "
        "{%0,%1,%2,%3},{%4,%5,%6,%7},{%8,%9},{%0,%1,%2,%3};"
        : "+f"(c[0]), "+f"(c[1]), "+f"(c[2]), "+f"(c[3])
        : "r"(a0), "r"(a1), "r"(a2), "r"(a3), "r"(b0), "r"(b1));
}

// ---------------- resets ----------------
__global__ void reset_graph() {
    int i = blockIdx.x * blockDim.x + threadIdx.x;
    if (i < NN) { g_degi[i] = 0; g_cur[i] = 0; }
}
__global__ void reset_bnstats() {
    int i = threadIdx.x;
    if (i < HID) { g_sum[i] = 0.f; g_sq[i] = 0.f; }
}
__global__ void reset_pool() {
    int i = blockIdx.x * blockDim.x + threadIdx.x;
    if (i < BB * 2 * HID) { g_p1[i] = 0.f; g_p2[i] = ENC_NEG_INF; }
    if (i < BB) g_cnt[i] = 0.f;
}

// ---------------- degree / norm ----------------
__global__ void degree_kernel(const int* __restrict__ eidx) {
    int i = blockIdx.x * blockDim.x + threadIdx.x;
    if (i < EE) atomicAdd(&g_degi[eidx[EE + i]], 1);
}
__global__ void norm_kernel(const int* __restrict__ eidx) {
    int i = blockIdx.x * blockDim.x + threadIdx.x;
    if (i >= EE) return;
    int dr = g_degi[eidx[i]];
    int dc = g_degi[eidx[EE + i]];
    float a = dr > 0 ? rsqrtf((float)dr) : 0.f;
    float b = dc > 0 ? rsqrtf((float)dc) : 0.f;
    g_norm[i] = a * b;
}

// ---------------- CSR build ----------------
__global__ void scan_block() {
    __shared__ int s[1024];
    int i = blockIdx.x * 1024 + threadIdx.x;
    int v = (i < NN) ? g_degi[i] : 0;
    s[threadIdx.x] = v;
    __syncthreads();
#pragma unroll
    for (int off = 1; off < 1024; off <<= 1) {
        int x = (threadIdx.x >= off) ? s[threadIdx.x - off] : 0;
        __syncthreads();
        s[threadIdx.x] += x;
        __syncthreads();
    }
    if (i < NN) g_offi[i] = s[threadIdx.x];
    if (threadIdx.x == 1023) g_bsum[blockIdx.x] = s[1023];
}
__global__ void scan_bsum() {
    if (threadIdx.x == 0) {
        int run = 0;
        for (int b = 0; b < SCAN_BLKS; b++) { int v = g_bsum[b]; g_bsum[b] = run; run += v; }
        g_offx[NN] = EE;
    }
}
__global__ void scan_fix() {
    int i = blockIdx.x * blockDim.x + threadIdx.x;
    if (i < NN) g_offx[i] = g_offi[i] - g_degi[i] + g_bsum[i >> 10];
}
__global__ void csr_fill(const int* __restrict__ eidx) {
    int e = blockIdx.x * 256 + threadIdx.x;
    int row = eidx[e], col = eidx[EE + e];
    int pos = g_offx[col] + atomicAdd(&g_cur[col], 1);
    g_csr[pos] = make_int2(row, __float_as_int(g_norm[e]));
}

// ---------------- input GEMM via tf32x3 MMA: dst = relu(in @ W + b) ----------------
// 96 thr = 3 warps x 24 cols; 64 rows/block = 4 m16 tiles.
template <int K, int DST>
__global__ __launch_bounds__(96) void gemm_in_mma(const float* __restrict__ in,
                                                  const float* __restrict__ W,
                                                  const float* __restrict__ bias) {
    float* __restrict__ out = (DST == 0) ? g_h : g_e;
    const int KT = K / 8;
    const int P = K + 4;
    __shared__ __align__(16) float s_in[64 * P];
    const int tid = threadIdx.x;
    const int warp = tid >> 5, lane = tid & 31;
    const int ln4 = lane >> 2, lm4 = lane & 3;
    const int row0 = blockIdx.x * 64;
    const int c0 = warp * 24;

    for (int idx = tid; idx < 64 * K; idx += 96) {
        int r = idx / K, c = idx - r * K;
        s_in[r * P + c] = (row0 + r < NN) ? in[(size_t)(row0 + r) * K + c] : 0.f;
    }
    __syncthreads();

    unsigned bh[KT][3][2], bl[KT][3][2];
#pragma unroll
    for (int kt = 0; kt < KT; kt++)
#pragma unroll
        for (int nt = 0; nt < 3; nt++) {
            int n = c0 + nt * 8 + ln4;
            tfsplit(W[(kt * 8 + lm4) * HID + n], bh[kt][nt][0], bl[kt][nt][0]);
            tfsplit(W[(kt * 8 + 4 + lm4) * HID + n], bh[kt][nt][1], bl[kt][nt][1]);
        }

    for (int rt = 0; rt < 4; rt++) {
        float acc[3][4] = {{0.f}};
#pragma unroll
        for (int kt = 0; kt < KT; kt++) {
            int rb = (rt * 16 + ln4) * P + kt * 8 + lm4;
            unsigned ah0, al0, ah1, al1, ah2, al2, ah3, al3;
            tfsplit(s_in[rb], ah0, al0);
            tfsplit(s_in[rb + 8 * P], ah1, al1);
            tfsplit(s_in[rb + 4], ah2, al2);
            tfsplit(s_in[rb + 8 * P + 4], ah3, al3);
#pragma unroll
            for (int nt = 0; nt < 3; nt++) {
                mma8(acc[nt], ah0, ah1, ah2, ah3, bh[kt][nt][0], bh[kt][nt][1]);
                mma8(acc[nt], ah0, ah1, ah2, ah3, bl[kt][nt][0], bl[kt][nt][1]);
                mma8(acc[nt], al0, al1, al2, al3, bh[kt][nt][0], bh[kt][nt][1]);
            }
        }
        int r_lo = row0 + rt * 16 + ln4, r_hi = r_lo + 8;
#pragma unroll
        for (int nt = 0; nt < 3; nt++) {
            int c = c0 + nt * 8 + lm4 * 2;
            float b0 = bias[c], b1 = bias[c + 1];
            if (r_lo < NN)
                *(float2*)&out[r_lo * HID + c] =
                    make_float2(fmaxf(acc[nt][0] + b0, 0.f), fmaxf(acc[nt][1] + b1, 0.f));
            if (r_hi < NN)
                *(float2*)&out[r_hi * HID + c] =
                    make_float2(fmaxf(acc[nt][2] + b0, 0.f), fmaxf(acc[nt][3] + b1, 0.f));
        }
    }
}

// ---------------- conv GEMMs via tf32x3 MMA: t = h@Wi ; acc = h@Wr + bias ------------
template <bool BN>
__global__ __launch_bounds__(96) void conv_mma(const float* __restrict__ Wi,
                                               const float* __restrict__ Wr,
                                               const float* __restrict__ bias) {
    const int K = HID, KT = 9, P = K + 4;
    __shared__ __align__(16) float s_in[64 * P];
    const int tid = threadIdx.x;
    const int warp = tid >> 5, lane = tid & 31;
    const int ln4 = lane >> 2, lm4 = lane & 3;
    const int row0 = blockIdx.x * 64;
    const int c0 = warp * 24;

    for (int idx = tid; idx < 64 * K; idx += 96) {
        int r = idx / K, c = idx - r * K;
        float v = (row0 + r < NN) ? g_h[(row0 + r) * K + c] : 0.f;
        if (BN) v = v * g_scale[c] + g_shift[c];
        s_in[r * P + c] = v;
    }
    __syncthreads();

    // ---- pass 1: Wi -> g_t (no bias) ----
    {
        unsigned bh[KT][3][2], bl[KT][3][2];
#pragma unroll
        for (int kt = 0; kt < KT; kt++)
#pragma unroll
            for (int nt = 0; nt < 3; nt++) {
                int n = c0 + nt * 8 + ln4;
                tfsplit(Wi[(kt * 8 + lm4) * HID + n], bh[kt][nt][0], bl[kt][nt][0]);
                tfsplit(Wi[(kt * 8 + 4 + lm4) * HID + n], bh[kt][nt][1], bl[kt][nt][1]);
            }
        for (int rt = 0; rt < 4; rt++) {
            float acc[3][4] = {{0.f}};
#pragma unroll
            for (int kt = 0; kt < KT; kt++) {
                int rb = (rt * 16 + ln4) * P + kt * 8 + lm4;
                unsigned ah0, al0, ah1, al1, ah2, al2, ah3, al3;
                tfsplit(s_in[rb], ah0, al0);
                tfsplit(s_in[rb + 8 * P], ah1, al1);
                tfsplit(s_in[rb + 4], ah2, al2);
                tfsplit(s_in[rb + 8 * P + 4], ah3, al3);
#pragma unroll
                for (int nt = 0; nt < 3; nt++) {
                    mma8(acc[nt], ah0, ah1, ah2, ah3, bh[kt][nt][0], bh[kt][nt][1]);
                    mma8(acc[nt], ah0, ah1, ah2, ah3, bl[kt][nt][0], bl[kt][nt][1]);
                    mma8(acc[nt], al0, al1, al2, al3, bh[kt][nt][0], bh[kt][nt][1]);
                }
            }
            int r_lo = row0 + rt * 16 + ln4, r_hi = r_lo + 8;
#pragma unroll
            for (int nt = 0; nt < 3; nt++) {
                int c = c0 + nt * 8 + lm4 * 2;
                if (r_lo < NN)
                    *(float2*)&g_t[r_lo * HID + c] = make_float2(acc[nt][0], acc[nt][1]);
                if (r_hi < NN)
                    *(float2*)&g_t[r_hi * HID + c] = make_float2(acc[nt][2], acc[nt][3]);
            }
        }
    }
    // ---- pass 2: Wr -> g_acc (+ bias) ----
    {
        unsigned bh[KT][3][2], bl[KT][3][2];
#pragma unroll
        for (int kt = 0; kt < KT; kt++)
#pragma unroll
            for (int nt = 0; nt < 3; nt++) {
                int n = c0 + nt * 8 + ln4;
                tfsplit(Wr[(kt * 8 + lm4) * HID + n], bh[kt][nt][0], bl[kt][nt][0]);
                tfsplit(Wr[(kt * 8 + 4 + lm4) * HID + n], bh[kt][nt][1], bl[kt][nt][1]);
            }
        for (int rt = 0; rt < 4; rt++) {
            float acc[3][4] = {{0.f}};
#pragma unroll
            for (int kt = 0; kt < KT; kt++) {
                int rb = (rt * 16 + ln4) * P + kt * 8 + lm4;
                unsigned ah0, al0, ah1, al1, ah2, al2, ah3, al3;
                tfsplit(s_in[rb], ah0, al0);
                tfsplit(s_in[rb + 8 * P], ah1, al1);
                tfsplit(s_in[rb + 4], ah2, al2);
                tfsplit(s_in[rb + 8 * P + 4], ah3, al3);
#pragma unroll
                for (int nt = 0; nt < 3; nt++) {
                    mma8(acc[nt], ah0, ah1, ah2, ah3, bh[kt][nt][0], bh[kt][nt][1]);
                    mma8(acc[nt], ah0, ah1, ah2, ah3, bl[kt][nt][0], bl[kt][nt][1]);
                    mma8(acc[nt], al0, al1, al2, al3, bh[kt][nt][0], bh[kt][nt][1]);
                }
            }
            int r_lo = row0 + rt * 16 + ln4, r_hi = r_lo + 8;
#pragma unroll
            for (int nt = 0; nt < 3; nt++) {
                int c = c0 + nt * 8 + lm4 * 2;
                float b0 = bias[c], b1 = bias[c + 1];
                if (r_lo < NN)
                    *(float2*)&g_acc[r_lo * HID + c] =
                        make_float2(acc[nt][0] + b0, acc[nt][1] + b1);
                if (r_hi < NN)
                    *(float2*)&g_acc[r_hi * HID + c] =
                        make_float2(acc[nt][2] + b0, acc[nt][3] + b1);
            }
        }
    }
}

// ---------------- gather: acc[n] += sum norm_e * t[src_e] ----------------
__global__ __launch_bounds__(288) void gather_edges() {
    int tid = threadIdx.x;
    int node = blockIdx.x * 16 + tid / 18;
    int ch = (tid % 18) * 4;
    if (node >= NN) return;
    int p = g_offx[node];
    int end = g_offx[node + 1];
    float* ap = g_acc + node * HID + ch;
    float4 acc = *(float4*)ap;
    if (p < end) {
        int2 rc = g_csr[p];
        for (; p < end; p++) {
            int2 nrc = (p + 1 < end) ? g_csr[p + 1] : rc;
            float nrm = __int_as_float(rc.y);
            float4 v = *(const float4*)(g_t + rc.x * HID + ch);
            acc.x += nrm * v.x; acc.y += nrm * v.y;
            acc.z += nrm * v.z; acc.w += nrm * v.w;
            rc = nrc;
        }
    }
    *(float4*)ap = acc;
}

// ---------------- batchnorm stats: h <- relu(acc); per-channel sum/sq ----------------
__global__ __launch_bounds__(288) void bn_stats() {
    int tid = threadIdx.x;
    int c = tid % HID, rg = tid / HID;
    float lsum = 0.f, lsq = 0.f;
    for (int r = blockIdx.x * 4 + rg; r < NN; r += gridDim.x * 4) {
        float v = fmaxf(g_acc[r * HID + c], 0.f);
        g_h[r * HID + c] = v;
        lsum += v; lsq += v * v;
    }
    __shared__ float ssum[288], ssq[288];
    ssum[tid] = lsum; ssq[tid] = lsq;
    __syncthreads();
    if (tid < HID) {
        float s = ssum[tid] + ssum[tid + 72] + ssum[tid + 144] + ssum[tid + 216];
        float q = ssq[tid] + ssq[tid + 72] + ssq[tid + 144] + ssq[tid + 216];
        atomicAdd(&g_sum[tid], s);
        atomicAdd(&g_sq[tid], q);
    }
}
__global__ void bn_finalize(const float* __restrict__ gamma, const float* __restrict__ beta) {
    int c = threadIdx.x;
    if (c >= HID) return;
    float mu = g_sum[c] * (1.0f / NN);
    float var = g_sq[c] * (1.0f / NN) - mu * mu;
    float inv = rsqrtf(var + EPSBN);
    float sc = inv * gamma[c];
    g_scale[c] = sc;
    g_shift[c] = beta[c] - mu * sc;
}

// ---------------- pooling (layer-3 BN fused into h read) ----------------
__global__ void pool_kernel(const float* __restrict__ assign) {
    int w = (blockIdx.x * blockDim.x + threadIdx.x) >> 5;
    int lane = threadIdx.x & 31;
    if (w >= NN) return;
    const float* a = assign + (size_t)w * BB;
    float best = -__int_as_float(0x7f800000);
    int bi = 0x7fffffff;
    for (int j = lane; j < BB; j += 32) {
        float v = a[j];
        if (v > best) { best = v; bi = j; }
    }
#pragma unroll
    for (int off = 16; off; off >>= 1) {
        float ov = __shfl_xor_sync(0xffffffffu, best, off);
        int oi = __shfl_xor_sync(0xffffffffu, bi, off);
        if (ov > best || (ov == best && oi < bi)) { best = ov; bi = oi; }
    }
    int b = bi;
    for (int c = lane; c < 2 * HID; c += 32) {
        float zv;
        if (c < HID) zv = g_h[w * HID + c] * g_scale[c] + g_shift[c];
        else         zv = g_e[w * HID + (c - HID)];
        atomicAdd(&g_p1[b * (2 * HID) + c], zv);
        atomicMax(&g_p2[b * (2 * HID) + c], fenc(zv));
    }
    if (lane == 0) atomicAdd(&g_cnt[b], 1.0f);
}

// ---------------- xp build + factored pair-MLP first layer ----------------
__global__ void xp_kernel(const float* __restrict__ w1, const float* __restrict__ b1) {
    __shared__ float s_xp[6 * HID];
    int b = blockIdx.x;
    int t = threadIdx.x;  // 144
    float cnt = g_cnt[b];
    float p1v = g_p1[b * 144 + t];
    s_xp[t] = p1v;
    s_xp[144 + t] = fdec(g_p2[b * 144 + t]);
    s_xp[288 + t] = p1v / fmaxf(cnt, 1.0f);
    __syncthreads();
    int j = (t < HID) ? t : t - HID;
    const float* w = (t < HID) ? w1 : (w1 + 6 * HID * HID);
    float acc = (t < HID) ? b1[j] : 0.f;
    for (int k = 0; k < 6 * HID; k++) acc += s_xp[k] * w[k * HID + j];
    if (t < HID) g_Ya[b * HID + j] = acc;
    else         g_Yb[b * HID + j] = acc;
}

// ---------------- pair output ----------------
__global__ void pair_kernel(const int* __restrict__ pe, const float* __restrict__ w2,
                            const float* __restrict__ b2, float* __restrict__ out) {
    int w = (blockIdx.x * blockDim.x + threadIdx.x) >> 5;
    int lane = threadIdx.x & 31;
    if (w >= EPN) return;
    int a = pe[w];
    int b = pe[EPN + w];
    float acc = 0.f;
    for (int c = lane; c < HID; c += 32) {
        float v = g_Ya[a * HID + c] + g_Yb[b * HID + c];
        acc += tanhf(v) * w2[c];
    }
#pragma unroll
    for (int off = 16; off; off >>= 1) acc += __shfl_xor_sync(0xffffffffu, acc, off);
    if (lane == 0) out[w] = acc + b2[0];
}

// ---------------- launch (conv_mma in profiled slot #4) ----------------
extern "C" void kernel_launch(void* const* d_in, const int* in_sizes, int n_in,
                              void* d_out, int out_size) {
    const float* x         = (const float*)d_in[0];
    const float* emb       = (const float*)d_in[1];
    const float* assign    = (const float*)d_in[2];
    const int*   eidx      = (const int*)d_in[3];
    const int*   pedge     = (const int*)d_in[4];
    const float* node_w    = (const float*)d_in[5];
    const float* node_b    = (const float*)d_in[6];
    const float* emb_w     = (const float*)d_in[7];
    const float* emb_b     = (const float*)d_in[8];
    const float* conv_wi   = (const float*)d_in[9];
    const float* conv_wr   = (const float*)d_in[10];
    const float* conv_bias = (const float*)d_in[11];
    const float* bn_gamma  = (const float*)d_in[12];
    const float* bn_beta   = (const float*)d_in[13];
    const float* mlp_w1    = (const float*)d_in[14];
    const float* mlp_b1    = (const float*)d_in[15];
    const float* mlp_w2    = (const float*)d_in[16];
    const float* mlp_b2    = (const float*)d_in[17];
    float*       out       = (float*)d_out;

    const int GB = (NN + 63) / 64;   // 1563

    reset_graph<<<(NN + 255) / 256, 256>>>();
    degree_kernel<<<EE / 256, 256>>>(eidx);
    gemm_in_mma<NINK, 0><<<GB, 96>>>(x, node_w, node_b);
    conv_mma<false><<<GB, 96>>>(conv_wi, conv_wr, conv_bias);   // profiled slot
    norm_kernel<<<EE / 256, 256>>>(eidx);
    scan_block<<<SCAN_BLKS, 1024>>>();
    scan_bsum<<<1, 32>>>();
    scan_fix<<<(NN + 255) / 256, 256>>>();
    csr_fill<<<EE / 256, 256>>>(eidx);
    gemm_in_mma<NINK, 1><<<GB, 96>>>(emb, emb_w, emb_b);

    reset_bnstats<<<1, 128>>>();
    gather_edges<<<(NN + 15) / 16, 288>>>();
    bn_stats<<<1024, 288>>>();
    bn_finalize<<<1, 128>>>(bn_gamma, bn_beta);

    for (int l = 1; l < 3; l++) {
        conv_mma<true><<<GB, 96>>>(conv_wi + l * HID * HID, conv_wr + l * HID * HID,
                                   conv_bias + l * HID);
        reset_bnstats<<<1, 128>>>();
        gather_edges<<<(NN + 15) / 16, 288>>>();
        bn_stats<<<1024, 288>>>();
        bn_finalize<<<1, 128>>>(bn_gamma + l * HID, bn_beta + l * HID);
    }

    reset_pool<<<(BB * 2 * HID + 255) / 256, 256>>>();
    pool_kernel<<<(NN * 32 + 255) / 256, 256>>>(assign);

    xp_kernel<<<BB, 144>>>(mlp_w1, mlp_b1);
    pair_kernel<<<(EPN * 32 + 255) / 256, 256>>>(pedge, mlp_w2, mlp_b2, out);
}

// round 15
// speedup vs baseline: 1.2205x; 1.0222x over previous
#include <cuda_runtime.h>
#include <cstdint>

#define NN   100000
#define EE   1600000
#define BB   512
#define EPN  200000
#define NINK 64
#define HID  72
#define EPSBN 1e-5f
#define SCAN_BLKS ((NN + 1023) / 1024)   // 98

// ---------------- scratch (device globals) ----------------
__device__ __align__(16) int      g_degi[NN];
__device__ __align__(16) int      g_cur[NN];
__device__ __align__(16) int      g_offi[NN];
__device__ __align__(16) int      g_offx[NN + 1];
__device__ __align__(16) int      g_bsum[SCAN_BLKS + 1];
__device__ __align__(16) float    g_norm[EE];
__device__ __align__(16) int2     g_csr[EE];       // (src row, norm bits), dest-sorted
__device__ __align__(16) float    g_h[NN * HID];
__device__ __align__(16) float    g_t[NN * HID];
__device__ __align__(16) float    g_acc[NN * HID];
__device__ __align__(16) float    g_e[NN * HID];
__device__ __align__(16) float    g_sum[HID];
__device__ __align__(16) float    g_sq[HID];
__device__ __align__(16) float    g_scale[HID];
__device__ __align__(16) float    g_shift[HID];
__device__ __align__(16) float    g_p1[BB * 2 * HID];
__device__ __align__(16) unsigned g_p2[BB * 2 * HID];
__device__ __align__(16) float    g_cnt[BB];
__device__ __align__(16) float    g_Ya[BB * HID];
__device__ __align__(16) float    g_Yb[BB * HID];

__device__ __forceinline__ unsigned fenc(float f) {
    unsigned u = __float_as_uint(f);
    return (u & 0x80000000u) ? ~u : (u | 0x80000000u);
}
__device__ __forceinline__ float fdec(unsigned u) {
    return (u & 0x80000000u) ? __uint_as_float(u ^ 0x80000000u) : __uint_as_float(~u);
}
#define ENC_NEG_INF 0x007FFFFFu

// ---------------- tf32 helpers ----------------
__device__ __forceinline__ void tfsplit(float x, unsigned& hi, unsigned& lo) {
    asm("cvt.rna.tf32.f32 %0, %1;" : "=r"(hi) : "f"(x));
    float r = x - __uint_as_float(hi);
    asm("cvt.rna.tf32.f32 %0, %1;" : "=r"(lo) : "f"(r));
}
__device__ __forceinline__ void mma8(float* c, unsigned a0, unsigned a1, unsigned a2,
                                     unsigned a3, unsigned b0, unsigned b1) {
    asm volatile(
        "mma.sync.aligned.m16n8k8.row.col.f32.tf32.tf32.f32 "
        "{%0,%1,%2,%3},{%4,%5,%6,%7},{%8,%9},{%0,%1,%2,%3};"
        : "+f"(c[0]), "+f"(c[1]), "+f"(c[2]), "+f"(c[3])
        : "r"(a0), "r"(a1), "r"(a2), "r"(a3), "r"(b0), "r"(b1));
}

// ---------------- resets ----------------
__global__ void reset_graph() {
    int i = blockIdx.x * blockDim.x + threadIdx.x;
    if (i < NN) { g_degi[i] = 0; g_cur[i] = 0; }
}
__global__ void reset_bnstats() {
    int i = threadIdx.x;
    if (i < HID) { g_sum[i] = 0.f; g_sq[i] = 0.f; }
}
__global__ void reset_pool() {
    int i = blockIdx.x * blockDim.x + threadIdx.x;
    if (i < BB * 2 * HID) { g_p1[i] = 0.f; g_p2[i] = ENC_NEG_INF; }
    if (i < BB) g_cnt[i] = 0.f;
}

// ---------------- degree / norm ----------------
__global__ void degree_kernel(const int* __restrict__ eidx) {
    int i = blockIdx.x * blockDim.x + threadIdx.x;
    if (i < EE) atomicAdd(&g_degi[eidx[EE + i]], 1);
}
__global__ void norm_kernel(const int* __restrict__ eidx) {
    int i = blockIdx.x * blockDim.x + threadIdx.x;
    if (i >= EE) return;
    int dr = g_degi[eidx[i]];
    int dc = g_degi[eidx[EE + i]];
    float a = dr > 0 ? rsqrtf((float)dr) : 0.f;
    float b = dc > 0 ? rsqrtf((float)dc) : 0.f;
    g_norm[i] = a * b;
}

// ---------------- CSR build ----------------
__global__ void scan_block() {
    __shared__ int s[1024];
    int i = blockIdx.x * 1024 + threadIdx.x;
    int v = (i < NN) ? g_degi[i] : 0;
    s[threadIdx.x] = v;
    __syncthreads();
#pragma unroll
    for (int off = 1; off < 1024; off <<= 1) {
        int x = (threadIdx.x >= off) ? s[threadIdx.x - off] : 0;
        __syncthreads();
        s[threadIdx.x] += x;
        __syncthreads();
    }
    if (i < NN) g_offi[i] = s[threadIdx.x];
    if (threadIdx.x == 1023) g_bsum[blockIdx.x] = s[1023];
}
__global__ void scan_bsum() {
    if (threadIdx.x == 0) {
        int run = 0;
        for (int b = 0; b < SCAN_BLKS; b++) { int v = g_bsum[b]; g_bsum[b] = run; run += v; }
        g_offx[NN] = EE;
    }
}
__global__ void scan_fix() {
    int i = blockIdx.x * blockDim.x + threadIdx.x;
    if (i < NN) g_offx[i] = g_offi[i] - g_degi[i] + g_bsum[i >> 10];
}
__global__ void csr_fill(const int* __restrict__ eidx) {
    int e = blockIdx.x * 256 + threadIdx.x;
    int row = eidx[e], col = eidx[EE + e];
    int pos = g_offx[col] + atomicAdd(&g_cur[col], 1);
    g_csr[pos] = make_int2(row, __float_as_int(g_norm[e]));
}

// ---------------- input GEMM via tf32x3 MMA (A pre-split in smem) ----------------
// 96 thr = 3 warps x 24 cols; 64 rows/block = 4 m16 tiles.
template <int K, int DST>
__global__ __launch_bounds__(96) void gemm_in_mma(const float* __restrict__ in,
                                                  const float* __restrict__ W,
                                                  const float* __restrict__ bias) {
    float* __restrict__ out = (DST == 0) ? g_h : g_e;
    const int KT = K / 8;
    const int P = K + 4;
    __shared__ __align__(16) unsigned s_hi[64 * P];
    __shared__ __align__(16) unsigned s_lo[64 * P];
    const int tid = threadIdx.x;
    const int warp = tid >> 5, lane = tid & 31;
    const int ln4 = lane >> 2, lm4 = lane & 3;
    const int row0 = blockIdx.x * 64;
    const int c0 = warp * 24;

    for (int idx = tid; idx < 64 * K; idx += 96) {
        int r = idx / K, c = idx - r * K;
        float v = (row0 + r < NN) ? in[(size_t)(row0 + r) * K + c] : 0.f;
        unsigned hi, lo;
        tfsplit(v, hi, lo);
        s_hi[r * P + c] = hi;
        s_lo[r * P + c] = lo;
    }
    __syncthreads();

    unsigned bh[KT][3][2], bl[KT][3][2];
#pragma unroll
    for (int kt = 0; kt < KT; kt++)
#pragma unroll
        for (int nt = 0; nt < 3; nt++) {
            int n = c0 + nt * 8 + ln4;
            tfsplit(W[(kt * 8 + lm4) * HID + n], bh[kt][nt][0], bl[kt][nt][0]);
            tfsplit(W[(kt * 8 + 4 + lm4) * HID + n], bh[kt][nt][1], bl[kt][nt][1]);
        }

    for (int rt = 0; rt < 4; rt++) {
        float acc[3][4] = {{0.f}};
#pragma unroll
        for (int kt = 0; kt < KT; kt++) {
            int rb = (rt * 16 + ln4) * P + kt * 8 + lm4;
            unsigned ah0 = s_hi[rb],          al0 = s_lo[rb];
            unsigned ah1 = s_hi[rb + 8 * P],  al1 = s_lo[rb + 8 * P];
            unsigned ah2 = s_hi[rb + 4],      al2 = s_lo[rb + 4];
            unsigned ah3 = s_hi[rb + 8 * P + 4], al3 = s_lo[rb + 8 * P + 4];
#pragma unroll
            for (int nt = 0; nt < 3; nt++) {
                mma8(acc[nt], ah0, ah1, ah2, ah3, bh[kt][nt][0], bh[kt][nt][1]);
                mma8(acc[nt], ah0, ah1, ah2, ah3, bl[kt][nt][0], bl[kt][nt][1]);
                mma8(acc[nt], al0, al1, al2, al3, bh[kt][nt][0], bh[kt][nt][1]);
            }
        }
        int r_lo = row0 + rt * 16 + ln4, r_hi = r_lo + 8;
#pragma unroll
        for (int nt = 0; nt < 3; nt++) {
            int c = c0 + nt * 8 + lm4 * 2;
            float b0 = bias[c], b1 = bias[c + 1];
            if (r_lo < NN)
                *(float2*)&out[r_lo * HID + c] =
                    make_float2(fmaxf(acc[nt][0] + b0, 0.f), fmaxf(acc[nt][1] + b1, 0.f));
            if (r_hi < NN)
                *(float2*)&out[r_hi * HID + c] =
                    make_float2(fmaxf(acc[nt][2] + b0, 0.f), fmaxf(acc[nt][3] + b1, 0.f));
        }
    }
}

// ---------------- conv GEMMs via tf32x3 MMA (A pre-split in smem) ------------
template <bool BN>
__global__ __launch_bounds__(96) void conv_mma(const float* __restrict__ Wi,
                                               const float* __restrict__ Wr,
                                               const float* __restrict__ bias) {
    const int K = HID, KT = 9, P = K + 4;
    __shared__ __align__(16) unsigned s_hi[64 * P];
    __shared__ __align__(16) unsigned s_lo[64 * P];
    const int tid = threadIdx.x;
    const int warp = tid >> 5, lane = tid & 31;
    const int ln4 = lane >> 2, lm4 = lane & 3;
    const int row0 = blockIdx.x * 64;
    const int c0 = warp * 24;

    for (int idx = tid; idx < 64 * K; idx += 96) {
        int r = idx / K, c = idx - r * K;
        float v = (row0 + r < NN) ? g_h[(row0 + r) * K + c] : 0.f;
        if (BN) v = v * g_scale[c] + g_shift[c];
        unsigned hi, lo;
        tfsplit(v, hi, lo);
        s_hi[r * P + c] = hi;
        s_lo[r * P + c] = lo;
    }
    __syncthreads();

    // ---- pass 1: Wi -> g_t (no bias) ----
    {
        unsigned bh[KT][3][2], bl[KT][3][2];
#pragma unroll
        for (int kt = 0; kt < KT; kt++)
#pragma unroll
            for (int nt = 0; nt < 3; nt++) {
                int n = c0 + nt * 8 + ln4;
                tfsplit(Wi[(kt * 8 + lm4) * HID + n], bh[kt][nt][0], bl[kt][nt][0]);
                tfsplit(Wi[(kt * 8 + 4 + lm4) * HID + n], bh[kt][nt][1], bl[kt][nt][1]);
            }
        for (int rt = 0; rt < 4; rt++) {
            float acc[3][4] = {{0.f}};
#pragma unroll
            for (int kt = 0; kt < KT; kt++) {
                int rb = (rt * 16 + ln4) * P + kt * 8 + lm4;
                unsigned ah0 = s_hi[rb],          al0 = s_lo[rb];
                unsigned ah1 = s_hi[rb + 8 * P],  al1 = s_lo[rb + 8 * P];
                unsigned ah2 = s_hi[rb + 4],      al2 = s_lo[rb + 4];
                unsigned ah3 = s_hi[rb + 8 * P + 4], al3 = s_lo[rb + 8 * P + 4];
#pragma unroll
                for (int nt = 0; nt < 3; nt++) {
                    mma8(acc[nt], ah0, ah1, ah2, ah3, bh[kt][nt][0], bh[kt][nt][1]);
                    mma8(acc[nt], ah0, ah1, ah2, ah3, bl[kt][nt][0], bl[kt][nt][1]);
                    mma8(acc[nt], al0, al1, al2, al3, bh[kt][nt][0], bh[kt][nt][1]);
                }
            }
            int r_lo = row0 + rt * 16 + ln4, r_hi = r_lo + 8;
#pragma unroll
            for (int nt = 0; nt < 3; nt++) {
                int c = c0 + nt * 8 + lm4 * 2;
                if (r_lo < NN)
                    *(float2*)&g_t[r_lo * HID + c] = make_float2(acc[nt][0], acc[nt][1]);
                if (r_hi < NN)
                    *(float2*)&g_t[r_hi * HID + c] = make_float2(acc[nt][2], acc[nt][3]);
            }
        }
    }
    // ---- pass 2: Wr -> g_acc (+ bias) ----
    {
        unsigned bh[KT][3][2], bl[KT][3][2];
#pragma unroll
        for (int kt = 0; kt < KT; kt++)
#pragma unroll
            for (int nt = 0; nt < 3; nt++) {
                int n = c0 + nt * 8 + ln4;
                tfsplit(Wr[(kt * 8 + lm4) * HID + n], bh[kt][nt][0], bl[kt][nt][0]);
                tfsplit(Wr[(kt * 8 + 4 + lm4) * HID + n], bh[kt][nt][1], bl[kt][nt][1]);
            }
        for (int rt = 0; rt < 4; rt++) {
            float acc[3][4] = {{0.f}};
#pragma unroll
            for (int kt = 0; kt < KT; kt++) {
                int rb = (rt * 16 + ln4) * P + kt * 8 + lm4;
                unsigned ah0 = s_hi[rb],          al0 = s_lo[rb];
                unsigned ah1 = s_hi[rb + 8 * P],  al1 = s_lo[rb + 8 * P];
                unsigned ah2 = s_hi[rb + 4],      al2 = s_lo[rb + 4];
                unsigned ah3 = s_hi[rb + 8 * P + 4], al3 = s_lo[rb + 8 * P + 4];
#pragma unroll
                for (int nt = 0; nt < 3; nt++) {
                    mma8(acc[nt], ah0, ah1, ah2, ah3, bh[kt][nt][0], bh[kt][nt][1]);
                    mma8(acc[nt], ah0, ah1, ah2, ah3, bl[kt][nt][0], bl[kt][nt][1]);
                    mma8(acc[nt], al0, al1, al2, al3, bh[kt][nt][0], bh[kt][nt][1]);
                }
            }
            int r_lo = row0 + rt * 16 + ln4, r_hi = r_lo + 8;
#pragma unroll
            for (int nt = 0; nt < 3; nt++) {
                int c = c0 + nt * 8 + lm4 * 2;
                float b0 = bias[c], b1 = bias[c + 1];
                if (r_lo < NN)
                    *(float2*)&g_acc[r_lo * HID + c] =
                        make_float2(acc[nt][0] + b0, acc[nt][1] + b1);
                if (r_hi < NN)
                    *(float2*)&g_acc[r_hi * HID + c] =
                        make_float2(acc[nt][2] + b0, acc[nt][3] + b1);
            }
        }
    }
}

// ---------------- gather: acc[n] += sum norm_e * t[src_e] ----------------
__global__ __launch_bounds__(288) void gather_edges() {
    int tid = threadIdx.x;
    int node = blockIdx.x * 16 + tid / 18;
    int ch = (tid % 18) * 4;
    if (node >= NN) return;
    int p = g_offx[node];
    int end = g_offx[node + 1];
    float* ap = g_acc + node * HID + ch;
    float4 acc = *(float4*)ap;
    if (p < end) {
        int2 rc = g_csr[p];
        for (; p < end; p++) {
            int2 nrc = (p + 1 < end) ? g_csr[p + 1] : rc;
            float nrm = __int_as_float(rc.y);
            float4 v = *(const float4*)(g_t + rc.x * HID + ch);
            acc.x += nrm * v.x; acc.y += nrm * v.y;
            acc.z += nrm * v.z; acc.w += nrm * v.w;
            rc = nrc;
        }
    }
    *(float4*)ap = acc;
}

// ---------------- batchnorm stats: h <- relu(acc); per-channel sum/sq ----------------
__global__ __launch_bounds__(288) void bn_stats() {
    int tid = threadIdx.x;
    int c = tid % HID, rg = tid / HID;
    float lsum = 0.f, lsq = 0.f;
    for (int r = blockIdx.x * 4 + rg; r < NN; r += gridDim.x * 4) {
        float v = fmaxf(g_acc[r * HID + c], 0.f);
        g_h[r * HID + c] = v;
        lsum += v; lsq += v * v;
    }
    __shared__ float ssum[288], ssq[288];
    ssum[tid] = lsum; ssq[tid] = lsq;
    __syncthreads();
    if (tid < HID) {
        float s = ssum[tid] + ssum[tid + 72] + ssum[tid + 144] + ssum[tid + 216];
        float q = ssq[tid] + ssq[tid + 72] + ssq[tid + 144] + ssq[tid + 216];
        atomicAdd(&g_sum[tid], s);
        atomicAdd(&g_sq[tid], q);
    }
}
__global__ void bn_finalize(const float* __restrict__ gamma, const float* __restrict__ beta) {
    int c = threadIdx.x;
    if (c >= HID) return;
    float mu = g_sum[c] * (1.0f / NN);
    float var = g_sq[c] * (1.0f / NN) - mu * mu;
    float inv = rsqrtf(var + EPSBN);
    float sc = inv * gamma[c];
    g_scale[c] = sc;
    g_shift[c] = beta[c] - mu * sc;
}

// ---------------- pooling (layer-3 BN fused into h read) ----------------
__global__ void pool_kernel(const float* __restrict__ assign) {
    int w = (blockIdx.x * blockDim.x + threadIdx.x) >> 5;
    int lane = threadIdx.x & 31;
    if (w >= NN) return;
    const float* a = assign + (size_t)w * BB;
    float best = -__int_as_float(0x7f800000);
    int bi = 0x7fffffff;
    for (int j = lane; j < BB; j += 32) {
        float v = a[j];
        if (v > best) { best = v; bi = j; }
    }
#pragma unroll
    for (int off = 16; off; off >>= 1) {
        float ov = __shfl_xor_sync(0xffffffffu, best, off);
        int oi = __shfl_xor_sync(0xffffffffu, bi, off);
        if (ov > best || (ov == best && oi < bi)) { best = ov; bi = oi; }
    }
    int b = bi;
    for (int c = lane; c < 2 * HID; c += 32) {
        float zv;
        if (c < HID) zv = g_h[w * HID + c] * g_scale[c] + g_shift[c];
        else         zv = g_e[w * HID + (c - HID)];
        atomicAdd(&g_p1[b * (2 * HID) + c], zv);
        atomicMax(&g_p2[b * (2 * HID) + c], fenc(zv));
    }
    if (lane == 0) atomicAdd(&g_cnt[b], 1.0f);
}

// ---------------- xp build + factored pair-MLP first layer ----------------
__global__ void xp_kernel(const float* __restrict__ w1, const float* __restrict__ b1) {
    __shared__ float s_xp[6 * HID];
    int b = blockIdx.x;
    int t = threadIdx.x;  // 144
    float cnt = g_cnt[b];
    float p1v = g_p1[b * 144 + t];
    s_xp[t] = p1v;
    s_xp[144 + t] = fdec(g_p2[b * 144 + t]);
    s_xp[288 + t] = p1v / fmaxf(cnt, 1.0f);
    __syncthreads();
    int j = (t < HID) ? t : t - HID;
    const float* w = (t < HID) ? w1 : (w1 + 6 * HID * HID);
    float acc = (t < HID) ? b1[j] : 0.f;
    for (int k = 0; k < 6 * HID; k++) acc += s_xp[k] * w[k * HID + j];
    if (t < HID) g_Ya[b * HID + j] = acc;
    else         g_Yb[b * HID + j] = acc;
}

// ---------------- pair output ----------------
__global__ void pair_kernel(const int* __restrict__ pe, const float* __restrict__ w2,
                            const float* __restrict__ b2, float* __restrict__ out) {
    int w = (blockIdx.x * blockDim.x + threadIdx.x) >> 5;
    int lane = threadIdx.x & 31;
    if (w >= EPN) return;
    int a = pe[w];
    int b = pe[EPN + w];
    float acc = 0.f;
    for (int c = lane; c < HID; c += 32) {
        float v = g_Ya[a * HID + c] + g_Yb[b * HID + c];
        acc += tanhf(v) * w2[c];
    }
#pragma unroll
    for (int off = 16; off; off >>= 1) acc += __shfl_xor_sync(0xffffffffu, acc, off);
    if (lane == 0) out[w] = acc + b2[0];
}

// ---------------- launch (conv_mma in profiled slot #4) ----------------
extern "C" void kernel_launch(void* const* d_in, const int* in_sizes, int n_in,
                              void* d_out, int out_size) {
    const float* x         = (const float*)d_in[0];
    const float* emb       = (const float*)d_in[1];
    const float* assign    = (const float*)d_in[2];
    const int*   eidx      = (const int*)d_in[3];
    const int*   pedge     = (const int*)d_in[4];
    const float* node_w    = (const float*)d_in[5];
    const float* node_b    = (const float*)d_in[6];
    const float* emb_w     = (const float*)d_in[7];
    const float* emb_b     = (const float*)d_in[8];
    const float* conv_wi   = (const float*)d_in[9];
    const float* conv_wr   = (const float*)d_in[10];
    const float* conv_bias = (const float*)d_in[11];
    const float* bn_gamma  = (const float*)d_in[12];
    const float* bn_beta   = (const float*)d_in[13];
    const float* mlp_w1    = (const float*)d_in[14];
    const float* mlp_b1    = (const float*)d_in[15];
    const float* mlp_w2    = (const float*)d_in[16];
    const float* mlp_b2    = (const float*)d_in[17];
    float*       out       = (float*)d_out;

    const int GB = (NN + 63) / 64;   // 1563

    reset_graph<<<(NN + 255) / 256, 256>>>();
    degree_kernel<<<EE / 256, 256>>>(eidx);
    gemm_in_mma<NINK, 0><<<GB, 96>>>(x, node_w, node_b);
    conv_mma<false><<<GB, 96>>>(conv_wi, conv_wr, conv_bias);   // profiled slot
    norm_kernel<<<EE / 256, 256>>>(eidx);
    scan_block<<<SCAN_BLKS, 1024>>>();
    scan_bsum<<<1, 32>>>();
    scan_fix<<<(NN + 255) / 256, 256>>>();
    csr_fill<<<EE / 256, 256>>>(eidx);
    gemm_in_mma<NINK, 1><<<GB, 96>>>(emb, emb_w, emb_b);

    reset_bnstats<<<1, 128>>>();
    gather_edges<<<(NN + 15) / 16, 288>>>();
    bn_stats<<<1024, 288>>>();
    bn_finalize<<<1, 128>>>(bn_gamma, bn_beta);

    for (int l = 1; l < 3; l++) {
        conv_mma<true><<<GB, 96>>>(conv_wi + l * HID * HID, conv_wr + l * HID * HID,
                                   conv_bias + l * HID);
        reset_bnstats<<<1, 128>>>();
        gather_edges<<<(NN + 15) / 16, 288>>>();
        bn_stats<<<1024, 288>>>();
        bn_finalize<<<1, 128>>>(bn_gamma + l * HID, bn_beta + l * HID);
    }

    reset_pool<<<(BB * 2 * HID + 255) / 256, 256>>>();
    pool_kernel<<<(NN * 32 + 255) / 256, 256>>>(assign);

    xp_kernel<<<BB, 144>>>(mlp_w1, mlp_b1);
    pair_kernel<<<(EPN * 32 + 255) / 256, 256>>>(pedge, mlp_w2, mlp_b2, out);
}

// round 16
// speedup vs baseline: 1.2432x; 1.0186x over previous
#include <cuda_runtime.h>
#include <cstdint>

#define NN   100000
#define EE   1600000
#define BB   512
#define EPN  200000
#define NINK 64
#define HID  72
#define EPSBN 1e-5f
#define SCAN_BLKS ((NN + 1023) / 1024)   // 98

// ---------------- scratch (device globals) ----------------
__device__ __align__(16) int      g_degi[NN];
__device__ __align__(16) int      g_cur[NN];
__device__ __align__(16) int      g_offi[NN];
__device__ __align__(16) int      g_offx[NN + 1];
__device__ __align__(16) int      g_bsum[SCAN_BLKS + 1];
__device__ __align__(16) float    g_norm[EE];
__device__ __align__(16) int2     g_csr[EE];       // (src row, norm bits), dest-sorted
__device__ __align__(16) float    g_h[NN * HID];
__device__ __align__(16) float    g_t[NN * HID];
__device__ __align__(16) float    g_acc[NN * HID];
__device__ __align__(16) float    g_e[NN * HID];
__device__ __align__(16) int      g_batch[NN];
__device__ __align__(16) float    g_sum[HID];
__device__ __align__(16) float    g_sq[HID];
__device__ __align__(16) float    g_scale[HID];
__device__ __align__(16) float    g_shift[HID];
__device__ __align__(16) float    g_p1[BB * 2 * HID];
__device__ __align__(16) unsigned g_p2[BB * 2 * HID];
__device__ __align__(16) float    g_cnt[BB];
__device__ __align__(16) float    g_Ya[BB * HID];
__device__ __align__(16) float    g_Yb[BB * HID];

__device__ __forceinline__ unsigned fenc(float f) {
    unsigned u = __float_as_uint(f);
    return (u & 0x80000000u) ? ~u : (u | 0x80000000u);
}
__device__ __forceinline__ float fdec(unsigned u) {
    return (u & 0x80000000u) ? __uint_as_float(u ^ 0x80000000u) : __uint_as_float(~u);
}
#define ENC_NEG_INF 0x007FFFFFu

// ---------------- tf32 helpers ----------------
__device__ __forceinline__ void tfsplit(float x, unsigned& hi, unsigned& lo) {
    asm("cvt.rna.tf32.f32 %0, %1;" : "=r"(hi) : "f"(x));
    float r = x - __uint_as_float(hi);
    asm("cvt.rna.tf32.f32 %0, %1;" : "=r"(lo) : "f"(r));
}
__device__ __forceinline__ void mma8(float* c, unsigned a0, unsigned a1, unsigned a2,
                                     unsigned a3, unsigned b0, unsigned b1) {
    asm volatile(
        "mma.sync.aligned.m16n8k8.row.col.f32.tf32.tf32.f32 "
        "{%0,%1,%2,%3},{%4,%5,%6,%7},{%8,%9},{%0,%1,%2,%3};"
        : "+f"(c[0]), "+f"(c[1]), "+f"(c[2]), "+f"(c[3])
        : "r"(a0), "r"(a1), "r"(a2), "r"(a3), "r"(b0), "r"(b1));
}

// ---------------- resets ----------------
__global__ void reset_graph() {
    int i = blockIdx.x * blockDim.x + threadIdx.x;
    if (i < NN) { g_degi[i] = 0; g_cur[i] = 0; }
}
__global__ void reset_bnstats() {
    int i = threadIdx.x;
    if (i < HID) { g_sum[i] = 0.f; g_sq[i] = 0.f; }
}
__global__ void reset_pool() {
    int i = blockIdx.x * blockDim.x + threadIdx.x;
    if (i < BB * 2 * HID) { g_p1[i] = 0.f; g_p2[i] = ENC_NEG_INF; }
    if (i < BB) g_cnt[i] = 0.f;
}

// ---------------- degree / norm ----------------
__global__ void degree_kernel(const int* __restrict__ eidx) {
    int i = blockIdx.x * blockDim.x + threadIdx.x;
    if (i < EE) atomicAdd(&g_degi[eidx[EE + i]], 1);
}
__global__ void norm_kernel(const int* __restrict__ eidx) {
    int i = blockIdx.x * blockDim.x + threadIdx.x;
    if (i >= EE) return;
    int dr = g_degi[eidx[i]];
    int dc = g_degi[eidx[EE + i]];
    float a = dr > 0 ? rsqrtf((float)dr) : 0.f;
    float b = dc > 0 ? rsqrtf((float)dc) : 0.f;
    g_norm[i] = a * b;
}

// ---------------- CSR build ----------------
__global__ void scan_block() {
    __shared__ int s[1024];
    int i = blockIdx.x * 1024 + threadIdx.x;
    int v = (i < NN) ? g_degi[i] : 0;
    s[threadIdx.x] = v;
    __syncthreads();
#pragma unroll
    for (int off = 1; off < 1024; off <<= 1) {
        int x = (threadIdx.x >= off) ? s[threadIdx.x - off] : 0;
        __syncthreads();
        s[threadIdx.x] += x;
        __syncthreads();
    }
    if (i < NN) g_offi[i] = s[threadIdx.x];
    if (threadIdx.x == 1023) g_bsum[blockIdx.x] = s[1023];
}
__global__ void scan_bsum() {
    if (threadIdx.x == 0) {
        int run = 0;
        for (int b = 0; b < SCAN_BLKS; b++) { int v = g_bsum[b]; g_bsum[b] = run; run += v; }
        g_offx[NN] = EE;
    }
}
__global__ void scan_fix() {
    int i = blockIdx.x * blockDim.x + threadIdx.x;
    if (i < NN) g_offx[i] = g_offi[i] - g_degi[i] + g_bsum[i >> 10];
}
__global__ void csr_fill(const int* __restrict__ eidx) {
    int e = blockIdx.x * 256 + threadIdx.x;
    int row = eidx[e], col = eidx[EE + e];
    int pos = g_offx[col] + atomicAdd(&g_cur[col], 1);
    g_csr[pos] = make_int2(row, __float_as_int(g_norm[e]));
}

// ---------------- input GEMM via tf32x3 MMA (A pre-split in smem) ----------------
template <int K, int DST>
__global__ __launch_bounds__(96) void gemm_in_mma(const float* __restrict__ in,
                                                  const float* __restrict__ W,
                                                  const float* __restrict__ bias) {
    float* __restrict__ out = (DST == 0) ? g_h : g_e;
    const int KT = K / 8;
    const int P = K + 4;
    __shared__ __align__(16) unsigned s_hi[64 * P];
    __shared__ __align__(16) unsigned s_lo[64 * P];
    const int tid = threadIdx.x;
    const int warp = tid >> 5, lane = tid & 31;
    const int ln4 = lane >> 2, lm4 = lane & 3;
    const int row0 = blockIdx.x * 64;
    const int c0 = warp * 24;

    for (int idx = tid; idx < 64 * K; idx += 96) {
        int r = idx / K, c = idx - r * K;
        float v = (row0 + r < NN) ? in[(size_t)(row0 + r) * K + c] : 0.f;
        unsigned hi, lo;
        tfsplit(v, hi, lo);
        s_hi[r * P + c] = hi;
        s_lo[r * P + c] = lo;
    }
    __syncthreads();

    unsigned bh[KT][3][2], bl[KT][3][2];
#pragma unroll
    for (int kt = 0; kt < KT; kt++)
#pragma unroll
        for (int nt = 0; nt < 3; nt++) {
            int n = c0 + nt * 8 + ln4;
            tfsplit(W[(kt * 8 + lm4) * HID + n], bh[kt][nt][0], bl[kt][nt][0]);
            tfsplit(W[(kt * 8 + 4 + lm4) * HID + n], bh[kt][nt][1], bl[kt][nt][1]);
        }

    for (int rt = 0; rt < 4; rt++) {
        float acc[3][4] = {{0.f}};
#pragma unroll
        for (int kt = 0; kt < KT; kt++) {
            int rb = (rt * 16 + ln4) * P + kt * 8 + lm4;
            unsigned ah0 = s_hi[rb],          al0 = s_lo[rb];
            unsigned ah1 = s_hi[rb + 8 * P],  al1 = s_lo[rb + 8 * P];
            unsigned ah2 = s_hi[rb + 4],      al2 = s_lo[rb + 4];
            unsigned ah3 = s_hi[rb + 8 * P + 4], al3 = s_lo[rb + 8 * P + 4];
#pragma unroll
            for (int nt = 0; nt < 3; nt++) {
                mma8(acc[nt], ah0, ah1, ah2, ah3, bh[kt][nt][0], bh[kt][nt][1]);
                mma8(acc[nt], ah0, ah1, ah2, ah3, bl[kt][nt][0], bl[kt][nt][1]);
                mma8(acc[nt], al0, al1, al2, al3, bh[kt][nt][0], bh[kt][nt][1]);
            }
        }
        int r_lo = row0 + rt * 16 + ln4, r_hi = r_lo + 8;
#pragma unroll
        for (int nt = 0; nt < 3; nt++) {
            int c = c0 + nt * 8 + lm4 * 2;
            float b0 = bias[c], b1 = bias[c + 1];
            if (r_lo < NN)
                *(float2*)&out[r_lo * HID + c] =
                    make_float2(fmaxf(acc[nt][0] + b0, 0.f), fmaxf(acc[nt][1] + b1, 0.f));
            if (r_hi < NN)
                *(float2*)&out[r_hi * HID + c] =
                    make_float2(fmaxf(acc[nt][2] + b0, 0.f), fmaxf(acc[nt][3] + b1, 0.f));
        }
    }
}

// ---------------- conv GEMMs via tf32x3 MMA (A pre-split in smem) ------------
template <bool BN>
__global__ __launch_bounds__(96) void conv_mma(const float* __restrict__ Wi,
                                               const float* __restrict__ Wr,
                                               const float* __restrict__ bias) {
    const int K = HID, KT = 9, P = K + 4;
    __shared__ __align__(16) unsigned s_hi[64 * P];
    __shared__ __align__(16) unsigned s_lo[64 * P];
    const int tid = threadIdx.x;
    const int warp = tid >> 5, lane = tid & 31;
    const int ln4 = lane >> 2, lm4 = lane & 3;
    const int row0 = blockIdx.x * 64;
    const int c0 = warp * 24;

    for (int idx = tid; idx < 64 * K; idx += 96) {
        int r = idx / K, c = idx - r * K;
        float v = (row0 + r < NN) ? g_h[(row0 + r) * K + c] : 0.f;
        if (BN) v = v * g_scale[c] + g_shift[c];
        unsigned hi, lo;
        tfsplit(v, hi, lo);
        s_hi[r * P + c] = hi;
        s_lo[r * P + c] = lo;
    }
    __syncthreads();

    // ---- pass 1: Wi -> g_t (no bias) ----
    {
        unsigned bh[KT][3][2], bl[KT][3][2];
#pragma unroll
        for (int kt = 0; kt < KT; kt++)
#pragma unroll
            for (int nt = 0; nt < 3; nt++) {
                int n = c0 + nt * 8 + ln4;
                tfsplit(Wi[(kt * 8 + lm4) * HID + n], bh[kt][nt][0], bl[kt][nt][0]);
                tfsplit(Wi[(kt * 8 + 4 + lm4) * HID + n], bh[kt][nt][1], bl[kt][nt][1]);
            }
        for (int rt = 0; rt < 4; rt++) {
            float acc[3][4] = {{0.f}};
#pragma unroll
            for (int kt = 0; kt < KT; kt++) {
                int rb = (rt * 16 + ln4) * P + kt * 8 + lm4;
                unsigned ah0 = s_hi[rb],          al0 = s_lo[rb];
                unsigned ah1 = s_hi[rb + 8 * P],  al1 = s_lo[rb + 8 * P];
                unsigned ah2 = s_hi[rb + 4],      al2 = s_lo[rb + 4];
                unsigned ah3 = s_hi[rb + 8 * P + 4], al3 = s_lo[rb + 8 * P + 4];
#pragma unroll
                for (int nt = 0; nt < 3; nt++) {
                    mma8(acc[nt], ah0, ah1, ah2, ah3, bh[kt][nt][0], bh[kt][nt][1]);
                    mma8(acc[nt], ah0, ah1, ah2, ah3, bl[kt][nt][0], bl[kt][nt][1]);
                    mma8(acc[nt], al0, al1, al2, al3, bh[kt][nt][0], bh[kt][nt][1]);
                }
            }
            int r_lo = row0 + rt * 16 + ln4, r_hi = r_lo + 8;
#pragma unroll
            for (int nt = 0; nt < 3; nt++) {
                int c = c0 + nt * 8 + lm4 * 2;
                if (r_lo < NN)
                    *(float2*)&g_t[r_lo * HID + c] = make_float2(acc[nt][0], acc[nt][1]);
                if (r_hi < NN)
                    *(float2*)&g_t[r_hi * HID + c] = make_float2(acc[nt][2], acc[nt][3]);
            }
        }
    }
    // ---- pass 2: Wr -> g_acc (+ bias) ----
    {
        unsigned bh[KT][3][2], bl[KT][3][2];
#pragma unroll
        for (int kt = 0; kt < KT; kt++)
#pragma unroll
            for (int nt = 0; nt < 3; nt++) {
                int n = c0 + nt * 8 + ln4;
                tfsplit(Wr[(kt * 8 + lm4) * HID + n], bh[kt][nt][0], bl[kt][nt][0]);
                tfsplit(Wr[(kt * 8 + 4 + lm4) * HID + n], bh[kt][nt][1], bl[kt][nt][1]);
            }
        for (int rt = 0; rt < 4; rt++) {
            float acc[3][4] = {{0.f}};
#pragma unroll
            for (int kt = 0; kt < KT; kt++) {
                int rb = (rt * 16 + ln4) * P + kt * 8 + lm4;
                unsigned ah0 = s_hi[rb],          al0 = s_lo[rb];
                unsigned ah1 = s_hi[rb + 8 * P],  al1 = s_lo[rb + 8 * P];
                unsigned ah2 = s_hi[rb + 4],      al2 = s_lo[rb + 4];
                unsigned ah3 = s_hi[rb + 8 * P + 4], al3 = s_lo[rb + 8 * P + 4];
#pragma unroll
                for (int nt = 0; nt < 3; nt++) {
                    mma8(acc[nt], ah0, ah1, ah2, ah3, bh[kt][nt][0], bh[kt][nt][1]);
                    mma8(acc[nt], ah0, ah1, ah2, ah3, bl[kt][nt][0], bl[kt][nt][1]);
                    mma8(acc[nt], al0, al1, al2, al3, bh[kt][nt][0], bh[kt][nt][1]);
                }
            }
            int r_lo = row0 + rt * 16 + ln4, r_hi = r_lo + 8;
#pragma unroll
            for (int nt = 0; nt < 3; nt++) {
                int c = c0 + nt * 8 + lm4 * 2;
                float b0 = bias[c], b1 = bias[c + 1];
                if (r_lo < NN)
                    *(float2*)&g_acc[r_lo * HID + c] =
                        make_float2(acc[nt][0] + b0, acc[nt][1] + b1);
                if (r_hi < NN)
                    *(float2*)&g_acc[r_hi * HID + c] =
                        make_float2(acc[nt][2] + b0, acc[nt][3] + b1);
            }
        }
    }
}

// ---------------- gather: acc[n] += sum norm_e * t[src_e] ----------------
__global__ __launch_bounds__(288) void gather_edges() {
    int tid = threadIdx.x;
    int node = blockIdx.x * 16 + tid / 18;
    int ch = (tid % 18) * 4;
    if (node >= NN) return;
    int p = g_offx[node];
    int end = g_offx[node + 1];
    float* ap = g_acc + node * HID + ch;
    float4 acc = *(float4*)ap;
    if (p < end) {
        int2 rc = g_csr[p];
        for (; p < end; p++) {
            int2 nrc = (p + 1 < end) ? g_csr[p + 1] : rc;
            float nrm = __int_as_float(rc.y);
            float4 v = *(const float4*)(g_t + rc.x * HID + ch);
            acc.x += nrm * v.x; acc.y += nrm * v.y;
            acc.z += nrm * v.z; acc.w += nrm * v.w;
            rc = nrc;
        }
    }
    *(float4*)ap = acc;
}

// ---------------- batchnorm stats: h <- relu(acc); per-channel sum/sq ----------------
__global__ __launch_bounds__(288) void bn_stats() {
    int tid = threadIdx.x;
    int c = tid % HID, rg = tid / HID;
    float lsum = 0.f, lsq = 0.f;
    for (int r = blockIdx.x * 4 + rg; r < NN; r += gridDim.x * 4) {
        float v = fmaxf(g_acc[r * HID + c], 0.f);
        g_h[r * HID + c] = v;
        lsum += v; lsq += v * v;
    }
    __shared__ float ssum[288], ssq[288];
    ssum[tid] = lsum; ssq[tid] = lsq;
    __syncthreads();
    if (tid < HID) {
        float s = ssum[tid] + ssum[tid + 72] + ssum[tid + 144] + ssum[tid + 216];
        float q = ssq[tid] + ssq[tid + 72] + ssq[tid + 144] + ssq[tid + 216];
        atomicAdd(&g_sum[tid], s);
        atomicAdd(&g_sq[tid], q);
    }
}
// computes scale/shift then zeroes stats for the next layer
__global__ void bn_finalize(const float* __restrict__ gamma, const float* __restrict__ beta) {
    int c = threadIdx.x;
    if (c >= HID) return;
    float mu = g_sum[c] * (1.0f / NN);
    float var = g_sq[c] * (1.0f / NN) - mu * mu;
    float inv = rsqrtf(var + EPSBN);
    float sc = inv * gamma[c];
    g_scale[c] = sc;
    g_shift[c] = beta[c] - mu * sc;
    g_sum[c] = 0.f;
    g_sq[c] = 0.f;
}

// ---------------- pooling split: argmax (independent) + scatter ----------------
__global__ void argmax_kernel(const float* __restrict__ assign) {
    int w = (blockIdx.x * blockDim.x + threadIdx.x) >> 5;
    int lane = threadIdx.x & 31;
    if (w >= NN) return;
    const float* a = assign + (size_t)w * BB;
    float best = -__int_as_float(0x7f800000);
    int bi = 0x7fffffff;
    for (int j = lane; j < BB; j += 32) {
        float v = a[j];
        if (v > best) { best = v; bi = j; }
    }
#pragma unroll
    for (int off = 16; off; off >>= 1) {
        float ov = __shfl_xor_sync(0xffffffffu, best, off);
        int oi = __shfl_xor_sync(0xffffffffu, bi, off);
        if (ov > best || (ov == best && oi < bi)) { best = ov; bi = oi; }
    }
    if (lane == 0) g_batch[w] = bi;
}
__global__ void pool_scatter() {
    int w = (blockIdx.x * blockDim.x + threadIdx.x) >> 5;
    int lane = threadIdx.x & 31;
    if (w >= NN) return;
    int b = g_batch[w];
    for (int c = lane; c < 2 * HID; c += 32) {
        float zv;
        if (c < HID) zv = g_h[w * HID + c] * g_scale[c] + g_shift[c];
        else         zv = g_e[w * HID + (c - HID)];
        atomicAdd(&g_p1[b * (2 * HID) + c], zv);
        atomicMax(&g_p2[b * (2 * HID) + c], fenc(zv));
    }
    if (lane == 0) atomicAdd(&g_cnt[b], 1.0f);
}

// ---------------- xp build + factored pair-MLP first layer ----------------
__global__ void xp_kernel(const float* __restrict__ w1, const float* __restrict__ b1) {
    __shared__ float s_xp[6 * HID];
    int b = blockIdx.x;
    int t = threadIdx.x;  // 144
    float cnt = g_cnt[b];
    float p1v = g_p1[b * 144 + t];
    s_xp[t] = p1v;
    s_xp[144 + t] = fdec(g_p2[b * 144 + t]);
    s_xp[288 + t] = p1v / fmaxf(cnt, 1.0f);
    __syncthreads();
    int j = (t < HID) ? t : t - HID;
    const float* w = (t < HID) ? w1 : (w1 + 6 * HID * HID);
    float acc = (t < HID) ? b1[j] : 0.f;
    for (int k = 0; k < 6 * HID; k++) acc += s_xp[k] * w[k * HID + j];
    if (t < HID) g_Ya[b * HID + j] = acc;
    else         g_Yb[b * HID + j] = acc;
}

// ---------------- pair output ----------------
__global__ void pair_kernel(const int* __restrict__ pe, const float* __restrict__ w2,
                            const float* __restrict__ b2, float* __restrict__ out) {
    int w = (blockIdx.x * blockDim.x + threadIdx.x) >> 5;
    int lane = threadIdx.x & 31;
    if (w >= EPN) return;
    int a = pe[w];
    int b = pe[EPN + w];
    float acc = 0.f;
    for (int c = lane; c < HID; c += 32) {
        float v = g_Ya[a * HID + c] + g_Yb[b * HID + c];
        acc += tanhf(v) * w2[c];
    }
#pragma unroll
    for (int off = 16; off; off >>= 1) acc += __shfl_xor_sync(0xffffffffu, acc, off);
    if (lane == 0) out[w] = acc + b2[0];
}

// ---------------- stream/event plumbing (created once; not device memory) ----------
static cudaStream_t g_s1 = nullptr, g_s2 = nullptr;
static cudaEvent_t  g_evFork = nullptr, g_evCsr = nullptr, g_evResets = nullptr,
                    g_evSide = nullptr;

// ---------------- launch ----------------
extern "C" void kernel_launch(void* const* d_in, const int* in_sizes, int n_in,
                              void* d_out, int out_size) {
    const float* x         = (const float*)d_in[0];
    const float* emb       = (const float*)d_in[1];
    const float* assign    = (const float*)d_in[2];
    const int*   eidx      = (const int*)d_in[3];
    const int*   pedge     = (const int*)d_in[4];
    const float* node_w    = (const float*)d_in[5];
    const float* node_b    = (const float*)d_in[6];
    const float* emb_w     = (const float*)d_in[7];
    const float* emb_b     = (const float*)d_in[8];
    const float* conv_wi   = (const float*)d_in[9];
    const float* conv_wr   = (const float*)d_in[10];
    const float* conv_bias = (const float*)d_in[11];
    const float* bn_gamma  = (const float*)d_in[12];
    const float* bn_beta   = (const float*)d_in[13];
    const float* mlp_w1    = (const float*)d_in[14];
    const float* mlp_b1    = (const float*)d_in[15];
    const float* mlp_w2    = (const float*)d_in[16];
    const float* mlp_b2    = (const float*)d_in[17];
    float*       out       = (float*)d_out;

    if (!g_s1) {
        cudaStreamCreateWithFlags(&g_s1, cudaStreamNonBlocking);
        cudaStreamCreateWithFlags(&g_s2, cudaStreamNonBlocking);
        cudaEventCreateWithFlags(&g_evFork, cudaEventDisableTiming);
        cudaEventCreateWithFlags(&g_evCsr, cudaEventDisableTiming);
        cudaEventCreateWithFlags(&g_evResets, cudaEventDisableTiming);
        cudaEventCreateWithFlags(&g_evSide, cudaEventDisableTiming);
    }

    const int GB = (NN + 63) / 64;   // 1563

    // ---- fork side streams from the (captured) main stream ----
    cudaEventRecord(g_evFork, 0);
    cudaStreamWaitEvent(g_s1, g_evFork, 0);
    cudaStreamWaitEvent(g_s2, g_evFork, 0);

    // ---- s2: graph prep (needs only eidx) ----
    reset_graph<<<(NN + 255) / 256, 256, 0, g_s2>>>();
    degree_kernel<<<EE / 256, 256, 0, g_s2>>>(eidx);
    norm_kernel<<<EE / 256, 256, 0, g_s2>>>(eidx);
    scan_block<<<SCAN_BLKS, 1024, 0, g_s2>>>();
    scan_bsum<<<1, 32, 0, g_s2>>>();
    scan_fix<<<(NN + 255) / 256, 256, 0, g_s2>>>();
    csr_fill<<<EE / 256, 256, 0, g_s2>>>(eidx);
    cudaEventRecord(g_evCsr, g_s2);

    // ---- s1: resets, assign argmax, emb GEMM (independent of conv chain) ----
    reset_bnstats<<<1, 128, 0, g_s1>>>();
    reset_pool<<<(BB * 2 * HID + 255) / 256, 256, 0, g_s1>>>();
    cudaEventRecord(g_evResets, g_s1);
    argmax_kernel<<<(NN * 32 + 255) / 256, 256, 0, g_s1>>>(assign);
    gemm_in_mma<NINK, 1><<<GB, 96, 0, g_s1>>>(emb, emb_w, emb_b);
    cudaEventRecord(g_evSide, g_s1);

    // ---- main chain ----
    gemm_in_mma<NINK, 0><<<GB, 96>>>(x, node_w, node_b);
    conv_mma<false><<<GB, 96>>>(conv_wi, conv_wr, conv_bias);
    cudaStreamWaitEvent(0, g_evCsr, 0);      // CSR ready
    cudaStreamWaitEvent(0, g_evResets, 0);   // bn stats zeroed
    gather_edges<<<(NN + 15) / 16, 288>>>();
    bn_stats<<<1024, 288>>>();
    bn_finalize<<<1, 128>>>(bn_gamma, bn_beta);

    for (int l = 1; l < 3; l++) {
        conv_mma<true><<<GB, 96>>>(conv_wi + l * HID * HID, conv_wr + l * HID * HID,
                                   conv_bias + l * HID);
        gather_edges<<<(NN + 15) / 16, 288>>>();
        bn_stats<<<1024, 288>>>();
        bn_finalize<<<1, 128>>>(bn_gamma + l * HID, bn_beta + l * HID);
    }

    // ---- join side stream, then pooling + pair MLP ----
    cudaStreamWaitEvent(0, g_evSide, 0);     // argmax, emb GEMM, pool resets done
    pool_scatter<<<(NN * 32 + 255) / 256, 256>>>();
    xp_kernel<<<BB, 144>>>(mlp_w1, mlp_b1);
    pair_kernel<<<(EPN * 32 + 255) / 256, 256>>>(pedge, mlp_w2, mlp_b2, out);
}